// round 10
// baseline (speedup 1.0000x reference)
#include <cuda_runtime.h>
#include <math.h>

#define NN   50000
#define EE   300000
#define TOTE (EE + NN)
#define GG   64
#define NB_SCAN 196   // ceil(NN/256)

typedef unsigned long long u64;

// ---------------- scratch (device globals; no allocation allowed) ----------
__device__ float4 g_xw4[NN * 64];   // x @ W   [N, 256] viewed as [N, 64] float4
__device__ float  g_as[NN * 2];
__device__ float  g_ad[NN * 2];
__device__ int    g_deg[NN];
__device__ int    g_off[NN];
__device__ int    g_woff[NN];
__device__ int    g_srcs[TOTE];
__device__ float  g_z[NN * 3];
__device__ int    g_bsum[256];

// ---------------- packed f32x2 helpers ---------------------------------------
__device__ __forceinline__ void fma2(u64& d, u64 a, u64 b) {
    asm("fma.rn.f32x2 %0, %1, %2, %0;" : "+l"(d) : "l"(a), "l"(b));
}
__device__ __forceinline__ u64 bcast2(float x) {
    u64 r;
    asm("mov.b64 %0, {%1, %1};" : "=l"(r) : "f"(x));
    return r;
}
__device__ __forceinline__ u64 pk2(float lo, float hi) {
    u64 r;
    asm("mov.b64 %0, {%1, %2};" : "=l"(r) : "f"(lo), "f"(hi));
    return r;
}
__device__ __forceinline__ void unpack2(u64 v, float& lo, float& hi) {
    asm("mov.b64 {%0, %1}, %2;" : "=f"(lo), "=f"(hi) : "l"(v));
}

// ---------------- kernels ----------------------------------------------------
__global__ void k_init() {
    int i = blockIdx.x * blockDim.x + threadIdx.x;
    if (i < NN) g_deg[i] = 0;
}

// degree histogram of targets
__global__ void k_deg(const int* __restrict__ ei) {
    int e = blockIdx.x * blockDim.x + threadIdx.x;
    if (e >= TOTE) return;
    int t = (e < EE) ? ei[EE + e] : (e - EE);
    if ((unsigned)t < NN) atomicAdd(&g_deg[t], 1);
}

// scan stage 1: per-block sums
__global__ void k_scan1() {
    __shared__ int sp[256];
    int t = threadIdx.x;
    int i = blockIdx.x * 256 + t;
    sp[t] = (i < NN) ? g_deg[i] : 0;
    __syncthreads();
    for (int off = 128; off; off >>= 1) {
        if (t < off) sp[t] += sp[t + off];
        __syncthreads();
    }
    if (t == 0) g_bsum[blockIdx.x] = sp[0];
}

// Tiled GEMM, f32x2 FMA, conflict-free W reads, 3 blocks/SM forced.
// Block: 64 nodes x 256 cols. Thread: 8 nodes x 8 cols
// (cols {tx*4..+3} head0, {128+tx*4..+3} head1). Fused a_s/a_d epilogue.
__global__ __launch_bounds__(256, 3) void k_gemm(const float* __restrict__ x,
                                                 const float* __restrict__ W,
                                                 const float* __restrict__ att_s,
                                                 const float* __restrict__ att_d) {
    extern __shared__ float sm[];
    float* xs = sm;                 // [128][68], xs[k*68 + node]
    float* ws = sm + 128 * 68;      // [32][256]

    int tid = threadIdx.x;
    int tx = tid & 31;
    int ty = tid >> 5;              // node group: nodes ty*8 .. +7
    int n0 = blockIdx.x * 64;

    // load x tile transposed (zero-pad past NN)
#pragma unroll
    for (int r = 0; r < 8; r++) {
        int lin4 = r * 256 + tid;
        int node = lin4 >> 5;
        int k = (lin4 & 31) * 4;
        float4 v = make_float4(0.f, 0.f, 0.f, 0.f);
        if (n0 + node < NN) v = ((const float4*)x)[(size_t)(n0 + node) * 32 + (lin4 & 31)];
        xs[(k + 0) * 68 + node] = v.x;
        xs[(k + 1) * 68 + node] = v.y;
        xs[(k + 2) * 68 + node] = v.z;
        xs[(k + 3) * 68 + node] = v.w;
    }

    u64 acc2[8][4];
#pragma unroll
    for (int i = 0; i < 8; i++)
#pragma unroll
        for (int j = 0; j < 4; j++) acc2[i][j] = 0ull;

    for (int kc = 0; kc < 4; kc++) {
        __syncthreads();
#pragma unroll
        for (int r = 0; r < 8; r++) {
            int lin4 = r * 256 + tid;
            ((float4*)ws)[lin4] = ((const float4*)W)[kc * 2048 + lin4];
        }
        __syncthreads();
#pragma unroll 4
        for (int k = 0; k < 32; k++) {
            const float* xr = &xs[(kc * 32 + k) * 68 + ty * 8];
            float4 a0 = *(const float4*)(xr);
            float4 a1 = *(const float4*)(xr + 4);
            float4 wa = *(const float4*)&ws[k * 256 + tx * 4];
            float4 wb = *(const float4*)&ws[k * 256 + 128 + tx * 4];
            u64 w0 = pk2(wa.x, wa.y), w1 = pk2(wa.z, wa.w);
            u64 w2 = pk2(wb.x, wb.y), w3 = pk2(wb.z, wb.w);
            float xv[8] = {a0.x, a0.y, a0.z, a0.w, a1.x, a1.y, a1.z, a1.w};
#pragma unroll
            for (int i = 0; i < 8; i++) {
                u64 xp = bcast2(xv[i]);      // one live broadcast pair at a time
                fma2(acc2[i][0], xp, w0);
                fma2(acc2[i][1], xp, w1);
                fma2(acc2[i][2], xp, w2);
                fma2(acc2[i][3], xp, w3);
            }
        }
    }

    // epilogue (att vectors loaded only now to keep loop registers small)
    float4 s0 = *(const float4*)&att_s[tx * 4];
    float4 s1 = *(const float4*)&att_s[128 + tx * 4];
    float4 d0 = *(const float4*)&att_d[tx * 4];
    float4 d1 = *(const float4*)&att_d[128 + tx * 4];
#pragma unroll
    for (int i = 0; i < 8; i++) {
        float a[8];
#pragma unroll
        for (int j = 0; j < 4; j++) unpack2(acc2[i][j], a[2 * j], a[2 * j + 1]);
        int node = n0 + ty * 8 + i;
        float sp0 = a[0] * s0.x + a[1] * s0.y + a[2] * s0.z + a[3] * s0.w;
        float sp1 = a[4] * s1.x + a[5] * s1.y + a[6] * s1.z + a[7] * s1.w;
        float dp0 = a[0] * d0.x + a[1] * d0.y + a[2] * d0.z + a[3] * d0.w;
        float dp1 = a[4] * d1.x + a[5] * d1.y + a[6] * d1.z + a[7] * d1.w;
#pragma unroll
        for (int off = 16; off; off >>= 1) {
            sp0 += __shfl_xor_sync(0xffffffffu, sp0, off);
            sp1 += __shfl_xor_sync(0xffffffffu, sp1, off);
            dp0 += __shfl_xor_sync(0xffffffffu, dp0, off);
            dp1 += __shfl_xor_sync(0xffffffffu, dp1, off);
        }
        if (node < NN) {
            g_xw4[(size_t)node * 64 + tx]      = make_float4(a[0], a[1], a[2], a[3]);
            g_xw4[(size_t)node * 64 + 32 + tx] = make_float4(a[4], a[5], a[6], a[7]);
            if (tx == 0) {
                g_as[2 * node]     = sp0;
                g_as[2 * node + 1] = sp1;
                g_ad[2 * node]     = dp0;
                g_ad[2 * node + 1] = dp1;
            }
        }
    }
}

// scan stage 2+3 fused
__global__ void k_scanB() {
    __shared__ int sb[256];
    __shared__ int sp[256];
    int t = threadIdx.x;
    int b = blockIdx.x;

    sb[t] = (t < NB_SCAN) ? g_bsum[t] : 0;
    __syncthreads();
    for (int off = 1; off < 256; off <<= 1) {
        int u = (t >= off) ? sb[t - off] : 0;
        __syncthreads();
        sb[t] += u;
        __syncthreads();
    }
    int base = (b == 0) ? 0 : sb[b - 1];

    int i = b * 256 + t;
    int v = (i < NN) ? g_deg[i] : 0;
    sp[t] = v;
    __syncthreads();
    for (int off = 1; off < 256; off <<= 1) {
        int u = (t >= off) ? sp[t - off] : 0;
        __syncthreads();
        sp[t] += u;
        __syncthreads();
    }
    int excl = sp[t] - v + base;
    if (i < NN) { g_off[i] = excl; g_woff[i] = excl; }
}

// scatter: sources grouped by target
__global__ void k_scatter(const int* __restrict__ ei) {
    int e = blockIdx.x * blockDim.x + threadIdx.x;
    if (e >= TOTE) return;
    int s, t;
    if (e < EE) { s = ei[e]; t = ei[EE + e]; }
    else        { s = t = e - EE; }
    if ((unsigned)t >= NN || (unsigned)s >= NN) return;
    int pos = atomicAdd(&g_woff[t], 1);
    if ((unsigned)pos < TOTE) g_srcs[pos] = s;
}

// fused node kernel, 2 warps per node (one per head). lane owns 4 cols.
// block: 8 warps = 4 nodes. FC partials combined across the warp pair via smem.
__global__ void k_node(const float* __restrict__ bias, const float* __restrict__ fcw,
                       const float* __restrict__ fcb) {
    __shared__ float zpart[8][3];
    int tid  = threadIdx.x;
    int lane = tid & 31;
    int winb = tid >> 5;                         // warp in block (0..7)
    int gw   = blockIdx.x * 8 + winb;            // global warp
    int n    = gw >> 1;                          // node
    int h    = gw & 1;                           // head (== winb & 1)
    // NN*2 warps == grid*8 exactly; no bounds check needed

    int off = g_off[n], deg = g_deg[n];
    float adh = g_ad[2 * n + h];

    // pass A: segment max for this head (leaky is monotone)
    float mas = -INFINITY;
    for (int i = lane; i < deg; i += 32)
        mas = fmaxf(mas, g_as[2 * g_srcs[off + i] + h]);
#pragma unroll
    for (int o = 16; o; o >>= 1)
        mas = fmaxf(mas, __shfl_xor_sync(0xffffffffu, mas, o));
    float m = mas + adh; m = m > 0.f ? m : 0.2f * m;

    float4 acc = make_float4(0.f, 0.f, 0.f, 0.f);
    float den = 0.f;

    for (int i0 = 0; i0 < deg; i0 += 32) {
        int cnt = min(32, deg - i0);
        int s = 0; float ex = 0.f;
        if (lane < cnt) {
            s = g_srcs[off + i0 + lane];
            float l = g_as[2 * s + h] + adh; l = l > 0.f ? l : 0.2f * l;
            ex = expf(l - m);
        }
        den += ex;

        // pipelined gather: load edge j+1 while accumulating edge j
        int s0i = __shfl_sync(0xffffffffu, s, 0);
        float4 v = g_xw4[(size_t)s0i * 64 + h * 32 + lane];
        for (int j = 0; j < cnt; j++) {
            float4 nv;
            if (j + 1 < cnt) {
                int sn = __shfl_sync(0xffffffffu, s, j + 1);
                nv = g_xw4[(size_t)sn * 64 + h * 32 + lane];
            }
            float e = __shfl_sync(0xffffffffu, ex, j);
            acc.x += e * v.x; acc.y += e * v.y;
            acc.z += e * v.z; acc.w += e * v.w;
            if (j + 1 < cnt) v = nv;
        }
    }
#pragma unroll
    for (int o = 16; o; o >>= 1)
        den += __shfl_xor_sync(0xffffffffu, den, o);
    float inv = 1.f / den;

    // FC partial over this head's 128 cols (lane owns 4)
    int cb = h * 128 + lane * 4;
    float4 b4 = *(const float4*)&bias[cb];
    float vv[4] = {acc.x * inv + b4.x, acc.y * inv + b4.y,
                   acc.z * inv + b4.z, acc.w * inv + b4.w};
    float z0 = 0.f, z1 = 0.f, z2 = 0.f;
#pragma unroll
    for (int mth = 0; mth < 4; mth++) {
        float val = vv[mth] > 0.f ? vv[mth] : 0.f;
        int k = cb + mth;
        z0 += val * fcw[k * 3 + 0];
        z1 += val * fcw[k * 3 + 1];
        z2 += val * fcw[k * 3 + 2];
    }
#pragma unroll
    for (int o = 16; o; o >>= 1) {
        z0 += __shfl_xor_sync(0xffffffffu, z0, o);
        z1 += __shfl_xor_sync(0xffffffffu, z1, o);
        z2 += __shfl_xor_sync(0xffffffffu, z2, o);
    }
    if (lane == 0) { zpart[winb][0] = z0; zpart[winb][1] = z1; zpart[winb][2] = z2; }
    __syncthreads();
    if (h == 0 && lane == 0) {
        float p0 = zpart[winb][0] + zpart[winb + 1][0] + fcb[0];
        float p1 = zpart[winb][1] + zpart[winb + 1][1] + fcb[1];
        float p2 = zpart[winb][2] + zpart[winb + 1][2] + fcb[2];
        float mx = fmaxf(p0, fmaxf(p1, p2));
        float ls = mx + logf(expf(p0 - mx) + expf(p1 - mx) + expf(p2 - mx));
        g_z[n * 3 + 0] = p0 - ls;
        g_z[n * 3 + 1] = p1 - ls;
        g_z[n * 3 + 2] = p2 - ls;
    }
}

// deterministic pool: batch sorted -> contiguous node range per graph.
__global__ void k_pool(const int* __restrict__ batch, const float* __restrict__ a,
                       float* __restrict__ out) {
    __shared__ float sz[3][256];
    int g = blockIdx.x;
    int t = threadIdx.x;
    int lo = 0, hi = NN;
    while (lo < hi) { int mid = (lo + hi) >> 1; if (batch[mid] < g) lo = mid + 1; else hi = mid; }
    int s0 = lo;
    hi = NN;
    while (lo < hi) { int mid = (lo + hi) >> 1; if (batch[mid] < g + 1) lo = mid + 1; else hi = mid; }
    int e0 = lo;

    float z0 = 0.f, z1 = 0.f, z2 = 0.f;
    for (int n = s0 + t; n < e0; n += 256) {
        z0 += g_z[n * 3 + 0];
        z1 += g_z[n * 3 + 1];
        z2 += g_z[n * 3 + 2];
    }
    sz[0][t] = z0; sz[1][t] = z1; sz[2][t] = z2;
    __syncthreads();
    for (int off = 128; off; off >>= 1) {
        if (t < off) {
            sz[0][t] += sz[0][t + off];
            sz[1][t] += sz[1][t + off];
            sz[2][t] += sz[2][t + off];
        }
        __syncthreads();
    }
    if (t == 0) {
        float sc = *a;
        float p0 = sc * sz[0][0], p1 = sc * sz[1][0], p2 = sc * sz[2][0];
        float mx = fmaxf(p0, fmaxf(p1, p2));
        float ls = mx + logf(expf(p0 - mx) + expf(p1 - mx) + expf(p2 - mx));
        out[g * 3 + 0] = p0 - ls;
        out[g * 3 + 1] = p1 - ls;
        out[g * 3 + 2] = p2 - ls;
    }
}

// ---------------- launch -----------------------------------------------------
extern "C" void kernel_launch(void* const* d_in, const int* in_sizes, int n_in,
                              void* d_out, int out_size) {
    const float* x     = (const float*)d_in[0];
    const int*   ei    = (const int*)d_in[1];
    const int*   batch = (const int*)d_in[2];
    const float* W     = (const float*)d_in[3];
    const float* att_s = (const float*)d_in[4];
    const float* att_d = (const float*)d_in[5];
    const float* bias  = (const float*)d_in[6];
    const float* fcw   = (const float*)d_in[7];
    const float* fcb   = (const float*)d_in[8];
    const float* a     = (const float*)d_in[9];
    float* out = (float*)d_out;

    const int SMEM = (128 * 68 + 32 * 256) * 4;   // 67584 B
    cudaFuncSetAttribute(k_gemm, cudaFuncAttributeMaxDynamicSharedMemorySize, SMEM);

    // order chosen so k_gemm is the 4th launch (ncu capture slot)
    k_init   <<<(NN + 255) / 256, 256>>>();
    k_deg    <<<(TOTE + 255) / 256, 256>>>(ei);
    k_scan1  <<<NB_SCAN, 256>>>();
    k_gemm   <<<(NN + 63) / 64, 256, SMEM>>>(x, W, att_s, att_d);   // 4th: profiled
    k_scanB  <<<NB_SCAN, 256>>>();
    k_scatter<<<(TOTE + 255) / 256, 256>>>(ei);
    k_node   <<<(NN * 2) / 8, 256>>>(bias, fcw, fcb);
    k_pool   <<<GG, 256>>>(batch, a, out);
}

// round 11
// speedup vs baseline: 1.5420x; 1.5420x over previous
#include <cuda_runtime.h>
#include <math.h>

#define NN   50000
#define EE   300000
#define TOTE (EE + NN)
#define GG   64
#define NB_SCAN 196   // ceil(NN/256)

typedef unsigned long long u64;

// ---------------- scratch (device globals; no allocation allowed) ----------
__device__ float4 g_xw4[NN * 64];   // x @ W   [N, 256] viewed as [N, 64] float4
__device__ float  g_as[NN * 2];
__device__ float  g_ad[NN * 2];
__device__ int    g_deg[NN];
__device__ int    g_off[NN];
__device__ int    g_woff[NN];
__device__ int    g_srcs[TOTE];
__device__ float  g_z[NN * 3];
__device__ int    g_bsum[256];

// ---------------- packed f32x2 helpers ---------------------------------------
__device__ __forceinline__ void fma2(u64& d, u64 a, u64 b) {
    asm("fma.rn.f32x2 %0, %1, %2, %0;" : "+l"(d) : "l"(a), "l"(b));
}
__device__ __forceinline__ u64 bcast2(float x) {
    u64 r;
    asm("mov.b64 %0, {%1, %1};" : "=l"(r) : "f"(x));
    return r;
}
__device__ __forceinline__ u64 pk2(float lo, float hi) {
    u64 r;
    asm("mov.b64 %0, {%1, %2};" : "=l"(r) : "f"(lo), "f"(hi));
    return r;
}
__device__ __forceinline__ void unpack2(u64 v, float& lo, float& hi) {
    asm("mov.b64 {%0, %1}, %2;" : "=f"(lo), "=f"(hi) : "l"(v));
}

// ---------------- kernels ----------------------------------------------------
__global__ void k_init() {
    int i = blockIdx.x * blockDim.x + threadIdx.x;
    if (i < NN) g_deg[i] = 0;
}

// degree histogram of targets
__global__ void k_deg(const int* __restrict__ ei) {
    int e = blockIdx.x * blockDim.x + threadIdx.x;
    if (e >= TOTE) return;
    int t = (e < EE) ? ei[EE + e] : (e - EE);
    if ((unsigned)t < NN) atomicAdd(&g_deg[t], 1);
}

// scan stage 1: per-block sums
__global__ void k_scan1() {
    __shared__ int sp[256];
    int t = threadIdx.x;
    int i = blockIdx.x * 256 + t;
    sp[t] = (i < NN) ? g_deg[i] : 0;
    __syncthreads();
    for (int off = 128; off; off >>= 1) {
        if (t < off) sp[t] += sp[t + off];
        __syncthreads();
    }
    if (t == 0) g_bsum[blockIdx.x] = sp[0];
}

// Tiled GEMM, f32x2 FMA, conflict-free W reads (round-9 version, 87us known).
__global__ __launch_bounds__(256) void k_gemm(const float* __restrict__ x,
                                              const float* __restrict__ W,
                                              const float* __restrict__ att_s,
                                              const float* __restrict__ att_d) {
    extern __shared__ float sm[];
    float* xs = sm;                 // [128][68], xs[k*68 + node]
    float* ws = sm + 128 * 68;      // [32][256]

    int tid = threadIdx.x;
    int tx = tid & 31;
    int ty = tid >> 5;              // node group: nodes ty*8 .. +7
    int n0 = blockIdx.x * 64;

    // load x tile transposed (zero-pad past NN)
#pragma unroll
    for (int r = 0; r < 8; r++) {
        int lin4 = r * 256 + tid;
        int node = lin4 >> 5;
        int k = (lin4 & 31) * 4;
        float4 v = make_float4(0.f, 0.f, 0.f, 0.f);
        if (n0 + node < NN) v = ((const float4*)x)[(size_t)(n0 + node) * 32 + (lin4 & 31)];
        xs[(k + 0) * 68 + node] = v.x;
        xs[(k + 1) * 68 + node] = v.y;
        xs[(k + 2) * 68 + node] = v.z;
        xs[(k + 3) * 68 + node] = v.w;
    }

    u64 acc2[8][4];
#pragma unroll
    for (int i = 0; i < 8; i++)
#pragma unroll
        for (int j = 0; j < 4; j++) acc2[i][j] = 0ull;

    for (int kc = 0; kc < 4; kc++) {
        __syncthreads();
#pragma unroll
        for (int r = 0; r < 8; r++) {
            int lin4 = r * 256 + tid;
            ((float4*)ws)[lin4] = ((const float4*)W)[kc * 2048 + lin4];
        }
        __syncthreads();
#pragma unroll 8
        for (int k = 0; k < 32; k++) {
            const float* xr = &xs[(kc * 32 + k) * 68 + ty * 8];
            float4 a0 = *(const float4*)(xr);
            float4 a1 = *(const float4*)(xr + 4);
            u64 xp[8] = {bcast2(a0.x), bcast2(a0.y), bcast2(a0.z), bcast2(a0.w),
                         bcast2(a1.x), bcast2(a1.y), bcast2(a1.z), bcast2(a1.w)};
            float4 wa = *(const float4*)&ws[k * 256 + tx * 4];
            float4 wb = *(const float4*)&ws[k * 256 + 128 + tx * 4];
            u64 w0 = pk2(wa.x, wa.y), w1 = pk2(wa.z, wa.w);
            u64 w2 = pk2(wb.x, wb.y), w3 = pk2(wb.z, wb.w);
#pragma unroll
            for (int i = 0; i < 8; i++) {
                fma2(acc2[i][0], xp[i], w0);
                fma2(acc2[i][1], xp[i], w1);
                fma2(acc2[i][2], xp[i], w2);
                fma2(acc2[i][3], xp[i], w3);
            }
        }
    }

    // epilogue: store xw + fused a_s/a_d (head0 = cols tx*4.., head1 = 128+tx*4..)
    float4 s0 = *(const float4*)&att_s[tx * 4];
    float4 s1 = *(const float4*)&att_s[128 + tx * 4];
    float4 d0 = *(const float4*)&att_d[tx * 4];
    float4 d1 = *(const float4*)&att_d[128 + tx * 4];
#pragma unroll
    for (int i = 0; i < 8; i++) {
        float a[8];
#pragma unroll
        for (int j = 0; j < 4; j++) unpack2(acc2[i][j], a[2 * j], a[2 * j + 1]);
        int node = n0 + ty * 8 + i;
        float sp0 = a[0] * s0.x + a[1] * s0.y + a[2] * s0.z + a[3] * s0.w;
        float sp1 = a[4] * s1.x + a[5] * s1.y + a[6] * s1.z + a[7] * s1.w;
        float dp0 = a[0] * d0.x + a[1] * d0.y + a[2] * d0.z + a[3] * d0.w;
        float dp1 = a[4] * d1.x + a[5] * d1.y + a[6] * d1.z + a[7] * d1.w;
#pragma unroll
        for (int off = 16; off; off >>= 1) {
            sp0 += __shfl_xor_sync(0xffffffffu, sp0, off);
            sp1 += __shfl_xor_sync(0xffffffffu, sp1, off);
            dp0 += __shfl_xor_sync(0xffffffffu, dp0, off);
            dp1 += __shfl_xor_sync(0xffffffffu, dp1, off);
        }
        if (node < NN) {
            g_xw4[(size_t)node * 64 + tx]      = make_float4(a[0], a[1], a[2], a[3]);
            g_xw4[(size_t)node * 64 + 32 + tx] = make_float4(a[4], a[5], a[6], a[7]);
            if (tx == 0) {
                g_as[2 * node]     = sp0;
                g_as[2 * node + 1] = sp1;
                g_ad[2 * node]     = dp0;
                g_ad[2 * node + 1] = dp1;
            }
        }
    }
}

// scan stage 2+3 fused
__global__ void k_scanB() {
    __shared__ int sb[256];
    __shared__ int sp[256];
    int t = threadIdx.x;
    int b = blockIdx.x;

    sb[t] = (t < NB_SCAN) ? g_bsum[t] : 0;
    __syncthreads();
    for (int off = 1; off < 256; off <<= 1) {
        int u = (t >= off) ? sb[t - off] : 0;
        __syncthreads();
        sb[t] += u;
        __syncthreads();
    }
    int base = (b == 0) ? 0 : sb[b - 1];

    int i = b * 256 + t;
    int v = (i < NN) ? g_deg[i] : 0;
    sp[t] = v;
    __syncthreads();
    for (int off = 1; off < 256; off <<= 1) {
        int u = (t >= off) ? sp[t - off] : 0;
        __syncthreads();
        sp[t] += u;
        __syncthreads();
    }
    int excl = sp[t] - v + base;
    if (i < NN) { g_off[i] = excl; g_woff[i] = excl; }
}

// scatter: sources grouped by target
__global__ void k_scatter(const int* __restrict__ ei) {
    int e = blockIdx.x * blockDim.x + threadIdx.x;
    if (e >= TOTE) return;
    int s, t;
    if (e < EE) { s = ei[e]; t = ei[EE + e]; }
    else        { s = t = e - EE; }
    if ((unsigned)t >= NN || (unsigned)s >= NN) return;
    int pos = atomicAdd(&g_woff[t], 1);
    if ((unsigned)pos < TOTE) g_srcs[pos] = s;
}

// fused node kernel, 2 warps per node (one per head). lane owns 4 cols.
__global__ void k_node(const float* __restrict__ bias, const float* __restrict__ fcw,
                       const float* __restrict__ fcb) {
    __shared__ float zpart[8][3];
    int tid  = threadIdx.x;
    int lane = tid & 31;
    int winb = tid >> 5;                         // warp in block (0..7)
    int gw   = blockIdx.x * 8 + winb;            // global warp
    int n    = gw >> 1;                          // node
    int h    = gw & 1;                           // head

    int off = g_off[n], deg = g_deg[n];
    float adh = g_ad[2 * n + h];

    // pass A: segment max for this head (leaky is monotone)
    float mas = -INFINITY;
    for (int i = lane; i < deg; i += 32)
        mas = fmaxf(mas, g_as[2 * g_srcs[off + i] + h]);
#pragma unroll
    for (int o = 16; o; o >>= 1)
        mas = fmaxf(mas, __shfl_xor_sync(0xffffffffu, mas, o));
    float m = mas + adh; m = m > 0.f ? m : 0.2f * m;

    float4 acc = make_float4(0.f, 0.f, 0.f, 0.f);
    float den = 0.f;

    for (int i0 = 0; i0 < deg; i0 += 32) {
        int cnt = min(32, deg - i0);
        int s = 0; float ex = 0.f;
        if (lane < cnt) {
            s = g_srcs[off + i0 + lane];
            float l = g_as[2 * s + h] + adh; l = l > 0.f ? l : 0.2f * l;
            ex = expf(l - m);
        }
        den += ex;

        // pipelined gather: load edge j+1 while accumulating edge j
        int s0i = __shfl_sync(0xffffffffu, s, 0);
        float4 v = g_xw4[(size_t)s0i * 64 + h * 32 + lane];
        for (int j = 0; j < cnt; j++) {
            float4 nv;
            if (j + 1 < cnt) {
                int sn = __shfl_sync(0xffffffffu, s, j + 1);
                nv = g_xw4[(size_t)sn * 64 + h * 32 + lane];
            }
            float e = __shfl_sync(0xffffffffu, ex, j);
            acc.x += e * v.x; acc.y += e * v.y;
            acc.z += e * v.z; acc.w += e * v.w;
            if (j + 1 < cnt) v = nv;
        }
    }
#pragma unroll
    for (int o = 16; o; o >>= 1)
        den += __shfl_xor_sync(0xffffffffu, den, o);
    float inv = 1.f / den;

    // FC partial over this head's 128 cols (lane owns 4)
    int cb = h * 128 + lane * 4;
    float4 b4 = *(const float4*)&bias[cb];
    float vv[4] = {acc.x * inv + b4.x, acc.y * inv + b4.y,
                   acc.z * inv + b4.z, acc.w * inv + b4.w};
    float z0 = 0.f, z1 = 0.f, z2 = 0.f;
#pragma unroll
    for (int mth = 0; mth < 4; mth++) {
        float val = vv[mth] > 0.f ? vv[mth] : 0.f;
        int k = cb + mth;
        z0 += val * fcw[k * 3 + 0];
        z1 += val * fcw[k * 3 + 1];
        z2 += val * fcw[k * 3 + 2];
    }
#pragma unroll
    for (int o = 16; o; o >>= 1) {
        z0 += __shfl_xor_sync(0xffffffffu, z0, o);
        z1 += __shfl_xor_sync(0xffffffffu, z1, o);
        z2 += __shfl_xor_sync(0xffffffffu, z2, o);
    }
    if (lane == 0) { zpart[winb][0] = z0; zpart[winb][1] = z1; zpart[winb][2] = z2; }
    __syncthreads();
    if (h == 0 && lane == 0) {
        float p0 = zpart[winb][0] + zpart[winb + 1][0] + fcb[0];
        float p1 = zpart[winb][1] + zpart[winb + 1][1] + fcb[1];
        float p2 = zpart[winb][2] + zpart[winb + 1][2] + fcb[2];
        float mx = fmaxf(p0, fmaxf(p1, p2));
        float ls = mx + logf(expf(p0 - mx) + expf(p1 - mx) + expf(p2 - mx));
        g_z[n * 3 + 0] = p0 - ls;
        g_z[n * 3 + 1] = p1 - ls;
        g_z[n * 3 + 2] = p2 - ls;
    }
}

// deterministic pool: batch sorted -> contiguous node range per graph.
__global__ void k_pool(const int* __restrict__ batch, const float* __restrict__ a,
                       float* __restrict__ out) {
    __shared__ float sz[3][256];
    int g = blockIdx.x;
    int t = threadIdx.x;
    int lo = 0, hi = NN;
    while (lo < hi) { int mid = (lo + hi) >> 1; if (batch[mid] < g) lo = mid + 1; else hi = mid; }
    int s0 = lo;
    hi = NN;
    while (lo < hi) { int mid = (lo + hi) >> 1; if (batch[mid] < g + 1) lo = mid + 1; else hi = mid; }
    int e0 = lo;

    float z0 = 0.f, z1 = 0.f, z2 = 0.f;
    for (int n = s0 + t; n < e0; n += 256) {
        z0 += g_z[n * 3 + 0];
        z1 += g_z[n * 3 + 1];
        z2 += g_z[n * 3 + 2];
    }
    sz[0][t] = z0; sz[1][t] = z1; sz[2][t] = z2;
    __syncthreads();
    for (int off = 128; off; off >>= 1) {
        if (t < off) {
            sz[0][t] += sz[0][t + off];
            sz[1][t] += sz[1][t + off];
            sz[2][t] += sz[2][t + off];
        }
        __syncthreads();
    }
    if (t == 0) {
        float sc = *a;
        float p0 = sc * sz[0][0], p1 = sc * sz[1][0], p2 = sc * sz[2][0];
        float mx = fmaxf(p0, fmaxf(p1, p2));
        float ls = mx + logf(expf(p0 - mx) + expf(p1 - mx) + expf(p2 - mx));
        out[g * 3 + 0] = p0 - ls;
        out[g * 3 + 1] = p1 - ls;
        out[g * 3 + 2] = p2 - ls;
    }
}

// ---------------- launch -----------------------------------------------------
extern "C" void kernel_launch(void* const* d_in, const int* in_sizes, int n_in,
                              void* d_out, int out_size) {
    const float* x     = (const float*)d_in[0];
    const int*   ei    = (const int*)d_in[1];
    const int*   batch = (const int*)d_in[2];
    const float* W     = (const float*)d_in[3];
    const float* att_s = (const float*)d_in[4];
    const float* att_d = (const float*)d_in[5];
    const float* bias  = (const float*)d_in[6];
    const float* fcw   = (const float*)d_in[7];
    const float* fcb   = (const float*)d_in[8];
    const float* a     = (const float*)d_in[9];
    float* out = (float*)d_out;

    const int SMEM = (128 * 68 + 32 * 256) * 4;   // 67584 B

    static cudaStream_t s2 = 0;
    static cudaEvent_t evA = 0, evB = 0;
    if (s2 == 0) {
        cudaStreamCreateWithFlags(&s2, cudaStreamNonBlocking);
        cudaEventCreateWithFlags(&evA, cudaEventDisableTiming);
        cudaEventCreateWithFlags(&evB, cudaEventDisableTiming);
        cudaFuncSetAttribute(k_gemm, cudaFuncAttributeMaxDynamicSharedMemorySize, SMEM);
    }

    // main stream: init -> gemm ; side stream: CSR chain (independent of gemm)
    k_init   <<<(NN + 255) / 256, 256>>>();
    cudaEventRecord(evA, 0);
    cudaStreamWaitEvent(s2, evA, 0);
    k_deg    <<<(TOTE + 255) / 256, 256, 0, s2>>>(ei);
    k_scan1  <<<NB_SCAN, 256, 0, s2>>>();
    k_gemm   <<<(NN + 63) / 64, 256, SMEM>>>(x, W, att_s, att_d);   // 4th submission: profiled
    k_scanB  <<<NB_SCAN, 256, 0, s2>>>();
    k_scatter<<<(TOTE + 255) / 256, 256, 0, s2>>>(ei);
    cudaEventRecord(evB, s2);
    cudaStreamWaitEvent(0, evB, 0);
    k_node   <<<(NN * 2) / 8, 256>>>(bias, fcw, fcb);
    k_pool   <<<GG, 256>>>(batch, a, out);
}